// round 13
// baseline (speedup 1.0000x reference)
#include <cuda_runtime.h>
#include <stdint.h>

// Problem constants
#define B 8
#define H 12
#define L 1024
#define D 768
#define KSEL 512
#define HL (H * L)                       // 12288 rows per batch
#define SPLITS 96
#define ROWS_PER_SPLIT (HL / SPLITS)     // 128
#define L4 (L / 4)                       // 256 float4 per score row
#define D4 (D / 4)                       // 192 float4 per token row
#define GBLK 65                          // gather blocks per batch

// Scratch (device globals). Zero at load; kernels restore zeros every call
// -> graph-replay safe.
__device__ float g_imp[B * L];
__device__ int   g_selidx[B * KSEL];
__device__ int   g_count[B];
__device__ int   g_flag[B];
__device__ int   g_done[B];

// ---------------------------------------------------------------------------
// Kernel 1 (the proven 73.8us colsum+select, plus: PDL trigger at entry and
// a per-batch release flag after compaction).
// grid (B, SPLITS), block 256.
// ---------------------------------------------------------------------------
__global__ void __launch_bounds__(256) colsum_select_kernel(
    const float4* __restrict__ scores4, const float* __restrict__ amask,
    float* __restrict__ imp, int* __restrict__ selidx,
    int* __restrict__ count, int* __restrict__ flag, float* __restrict__ out)
{
    // Let the dependent gather grid dispatch into leftover SM slots NOW.
#if __CUDA_ARCH__ >= 900
    cudaTriggerProgrammaticLaunchCompletion();
#endif

    const int b = blockIdx.x;
    const int s = blockIdx.y;
    const int t = threadIdx.x;
    const int lane = t & 31;
    const int wid  = t >> 5;

    // ---- colsum phase: stream 128 rows, accumulate 1 float4 per thread ----
    {
        const float4* base =
            scores4 + ((size_t)b * HL + (size_t)s * ROWS_PER_SPLIT) * L4 + t;
        float4 acc = make_float4(0.f, 0.f, 0.f, 0.f);
#pragma unroll 16
        for (int r = 0; r < ROWS_PER_SPLIT; ++r) {
            const float4 x = __ldcs(base + (size_t)r * L4);
            acc.x += x.x; acc.y += x.y; acc.z += x.z; acc.w += x.w;
        }
        float* dst = imp + b * L + 4 * t;
        atomicAdd(dst + 0, acc.x);
        atomicAdd(dst + 1, acc.y);
        atomicAdd(dst + 2, acc.z);
        atomicAdd(dst + 3, acc.w);
    }

    // ---- arrival: last block per batch runs the selection ----
    __threadfence();
    __syncthreads();
    __shared__ int s_ticket;
    if (t == 0) s_ticket = atomicAdd(&count[b], 1);
    __syncthreads();
    if (s_ticket != SPLITS - 1) return;
    __threadfence();               // acquire: all batch-b atomics visible

    // ---- read importance: thread t owns columns 4t..4t+3 ----
    const float4 iv = *((const float4*)(imp + b * L) + t);

    unsigned k[4];
    {
        const float f[4] = {iv.x, iv.y, iv.z, iv.w};
#pragma unroll
        for (int i = 0; i < 4; ++i) {
            const unsigned ub = __float_as_uint(f[i]);
            k[i] = ub ^ ((ub & 0x80000000u) ? 0xFFFFFFFFu : 0x80000000u);
        }
    }

    __shared__ int      hist[256];
    __shared__ unsigned s_pref;
    __shared__ int      s_k;
    __shared__ int      wtot[8];

    if (t == 0) { s_pref = 0u; s_k = KSEL; }
    __syncthreads();

    // ---- 4-pass byte radix select: 512th-largest key + tie quota ----
#pragma unroll
    for (int pass = 0; pass < 4; ++pass) {
        const int shift = 24 - 8 * pass;
        const unsigned pref = s_pref;
        const int kcur = s_k;

        hist[t] = 0;
        __syncthreads();
#pragma unroll
        for (int i = 0; i < 4; ++i) {
            const bool active = (pass == 0) ||
                (((k[i] ^ pref) >> (shift + 8)) == 0u);
            if (active) atomicAdd(&hist[(k[i] >> shift) & 0xFF], 1);
        }
        __syncthreads();

        const int h = hist[t];
        int v = h;
#pragma unroll
        for (int d = 1; d < 32; d <<= 1) {
            const int n = __shfl_down_sync(0xffffffffu, v, d);
            if (lane + d < 32) v += n;
        }
        const int wsum = __shfl_sync(0xffffffffu, v, 0);
        if (lane == 0) wtot[wid] = wsum;
        __syncthreads();
        int above = 0;
#pragma unroll
        for (int w = 0; w < 8; ++w) if (w > wid) above += wtot[w];
        const int ge = v + above;        // active keys with bin >= t
        const int gt = ge - h;
        if (gt < kcur && ge >= kcur) {   // exactly one bin fires
            s_pref = pref | ((unsigned)t << shift);
            s_k    = kcur - gt;
        }
        __syncthreads();
    }

    const unsigned T  = s_pref;   // threshold key (512th-largest)
    const int      kq = s_k;      // tie slots (>= 1), lowest indices win

    // ---- tie ranking (ascending index) via block scan ----
    bool tie[4];
    int tiecnt = 0;
#pragma unroll
    for (int i = 0; i < 4; ++i) { tie[i] = (k[i] == T); tiecnt += tie[i]; }

    int incl = tiecnt;
#pragma unroll
    for (int d = 1; d < 32; d <<= 1) {
        const int n = __shfl_up_sync(0xffffffffu, incl, d);
        if (lane >= d) incl += n;
    }
    if (lane == 31) wtot[wid] = incl;
    __syncthreads();
    int base = 0;
#pragma unroll
    for (int w = 0; w < 8; ++w) if (w < wid) base += wtot[w];
    int trank = base + incl - tiecnt;    // exclusive prefix of ties

    bool sel[4];
    int selcnt = 0;
#pragma unroll
    for (int i = 0; i < 4; ++i) {
        bool sl = (k[i] > T);
        if (tie[i]) { sl = (trank < kq); ++trank; }
        sel[i] = sl; selcnt += sl;
    }
    __syncthreads();                     // wtot reuse

    // ---- compaction scan (ascending index) ----
    int sincl = selcnt;
#pragma unroll
    for (int d = 1; d < 32; d <<= 1) {
        const int n = __shfl_up_sync(0xffffffffu, sincl, d);
        if (lane >= d) sincl += n;
    }
    if (lane == 31) wtot[wid] = sincl;
    __syncthreads();
    int sbase = 0;
#pragma unroll
    for (int w = 0; w < 8; ++w) if (w < wid) sbase += wtot[w];
    int pos = sbase + sincl - selcnt;    // exclusive prefix

#pragma unroll
    for (int i = 0; i < 4; ++i) {
        if (sel[i]) { selidx[b * KSEL + pos] = 4 * t + i; ++pos; }
    }

    // ---- release: selidx complete -> wake parked gather blocks ----
    __threadfence();
    __syncthreads();
    if (t == 0) atomicExch(&flag[b], 1);

    // ---- final attention mask for this batch (513 floats) ----
    float* mout = out + (size_t)B * (KSEL + 1) * D + (size_t)b * (KSEL + 1);
    for (int r = t; r <= KSEL; r += 256) {
        if (r == 0) mout[0] = 0.f;
        else        mout[r] = amask[(size_t)b * L + selidx[b * KSEL + r - 1]];
    }

    // ---- reset scratch for the next replay ----
    *((float4*)(imp + b * L) + t) = make_float4(0.f, 0.f, 0.f, 0.f);
    if (t == 0) count[b] = 0;
}

// ---------------------------------------------------------------------------
// Kernel 2 (PDL co-scheduled): blocks park in the SM slots kernel 1 leaves
// idle, sleep on flag[b], then gather 8 token rows each the moment their
// batch's selidx is released. No cudaGridDependencySynchronize (that would
// serialize); ordering via flag + fence.
// grid (GBLK, B), block 256: 8 rows/block, 32 lanes/row, 6 indep float4.
// ---------------------------------------------------------------------------
__global__ void __launch_bounds__(256) gather_kernel(
    const float* __restrict__ hs, const int* __restrict__ selidx,
    int* __restrict__ flag, int* __restrict__ done, float* __restrict__ out)
{
    const int b = blockIdx.y;
    const int t = threadIdx.x;

    // park until this batch's selidx is published
    if (t == 0) {
        unsigned ns = 64;
        while (((volatile int*)flag)[b] == 0) {
            __nanosleep(ns);
            if (ns < 2048) ns <<= 1;
        }
    }
    __syncthreads();
    __threadfence();   // acquire selidx

    const int rr   = t >> 5;                  // 0..7 row slot
    const int lane = t & 31;                  // 0..31
    const int r = blockIdx.x * 8 + rr;        // 0..527
    if (r <= KSEL) {
        const int j = (r == 0) ? 0 : selidx[b * KSEL + r - 1];

        const float4* src = (const float4*)(hs + ((size_t)b * L + j) * D)
                            + lane;
        float4* dst = (float4*)(out + ((size_t)b * (KSEL + 1) + r) * D)
                      + lane;

        float4 v[6];
#pragma unroll
        for (int q = 0; q < 6; ++q) v[q] = src[32 * q];
#pragma unroll
        for (int q = 0; q < 6; ++q) __stcs(dst + 32 * q, v[q]);
    }

    // last finishing block of this batch resets the flags for next replay
    __syncthreads();
    if (t == 0) {
        if (atomicAdd(&done[b], 1) == GBLK - 1) {
            done[b] = 0;
            flag[b] = 0;
        }
    }
}

// ---------------------------------------------------------------------------
extern "C" void kernel_launch(void* const* d_in, const int* in_sizes, int n_in,
                              void* d_out, int out_size)
{
    const float* hidden = (const float*)d_in[0];   // [B, L, D]
    const float* amask  = (const float*)d_in[1];   // [B, 1, 1, L]
    const float* scores = (const float*)d_in[2];   // [B, H, L, L]
    float* out = (float*)d_out;                    // tokens then mask, f32

    float* d_imp;
    int *d_selidx, *d_count, *d_flag, *d_done;
    cudaGetSymbolAddress((void**)&d_imp,    g_imp);
    cudaGetSymbolAddress((void**)&d_selidx, g_selidx);
    cudaGetSymbolAddress((void**)&d_count,  g_count);
    cudaGetSymbolAddress((void**)&d_flag,   g_flag);
    cudaGetSymbolAddress((void**)&d_done,   g_done);

    dim3 gridA(B, SPLITS);
    colsum_select_kernel<<<gridA, 256>>>(
        (const float4*)scores, amask, d_imp, d_selidx, d_count, d_flag, out);

    // Gather: programmatic dependent launch; kernel 1 triggers at entry, so
    // these blocks co-schedule into idle SM slots and park on flag[b].
    cudaLaunchAttribute attrs[1];
    attrs[0].id = cudaLaunchAttributeProgrammaticStreamSerialization;
    attrs[0].val.programmaticStreamSerializationAllowed = 1;

    cudaLaunchConfig_t cfg = {};
    cfg.gridDim  = dim3(GBLK, B);
    cfg.blockDim = dim3(256);
    cfg.dynamicSmemBytes = 0;
    cfg.stream = 0;
    cfg.attrs = attrs;
    cfg.numAttrs = 1;
    cudaLaunchKernelEx(&cfg, gather_kernel, hidden,
                       (const int*)d_selidx, d_flag, d_done, out);
}

// round 14
// speedup vs baseline: 1.0559x; 1.0559x over previous
#include <cuda_runtime.h>
#include <stdint.h>

// Problem constants
#define B 8
#define H 12
#define L 1024
#define D 768
#define KSEL 512
#define HL (H * L)                       // 12288 rows per batch
#define SPLITS 96
#define ROWS_PER_SPLIT (HL / SPLITS)     // 128
#define L4 (L / 4)                       // 256 float4 per score row
#define D4 (D / 4)                       // 192 float4 per token row
#define HID_BYTES ((size_t)B * L * D * 4)   // 25,165,824 = 768 * 32768

// Scratch (device globals). Zero at load; kernel restores zeros every call
// -> graph-replay safe.
__device__ float g_imp[B * L];
__device__ int   g_selidx[B * KSEL];
__device__ int   g_count[B];

// ---------------------------------------------------------------------------
// Kernel 1 (the proven 73.8us colsum+select, plus an L2 prefetch of hidden):
// column sums (96-way split, float4 streaming, f32 atomics into g_imp);
// per-batch last-arriving block runs the radix top-K select + compact and
// writes the final attention mask. grid (B, SPLITS), block 256.
// ---------------------------------------------------------------------------
__global__ void __launch_bounds__(256) colsum_select_kernel(
    const float4* __restrict__ scores4, const float* __restrict__ amask,
    const char* __restrict__ hidden_bytes,
    float* __restrict__ imp, int* __restrict__ selidx,
    int* __restrict__ count, float* __restrict__ out)
{
    const int b = blockIdx.x;
    const int s = blockIdx.y;
    const int t = threadIdx.x;
    const int lane = t & 31;
    const int wid  = t >> 5;

    // ---- L2 prefetch of hidden_states (one 128B line per thread; the 768
    //      blocks cover the 25.2MB array exactly). Scores stream with
    //      __ldcs (evict-first), so hidden stays L2-resident for gather. ----
    {
        const size_t off = ((size_t)(b * SPLITS + s) << 15) + ((size_t)t << 7);
        asm volatile("prefetch.global.L2 [%0];" :: "l"(hidden_bytes + off));
    }

    // ---- colsum phase: stream 128 rows, accumulate 1 float4 per thread ----
    {
        const float4* base =
            scores4 + ((size_t)b * HL + (size_t)s * ROWS_PER_SPLIT) * L4 + t;
        float4 acc = make_float4(0.f, 0.f, 0.f, 0.f);
#pragma unroll 16
        for (int r = 0; r < ROWS_PER_SPLIT; ++r) {
            const float4 x = __ldcs(base + (size_t)r * L4);
            acc.x += x.x; acc.y += x.y; acc.z += x.z; acc.w += x.w;
        }
        float* dst = imp + b * L + 4 * t;
        atomicAdd(dst + 0, acc.x);
        atomicAdd(dst + 1, acc.y);
        atomicAdd(dst + 2, acc.z);
        atomicAdd(dst + 3, acc.w);
    }

    // ---- arrival: last block per batch runs the selection ----
    __threadfence();
    __syncthreads();
    __shared__ int s_ticket;
    if (t == 0) s_ticket = atomicAdd(&count[b], 1);
    __syncthreads();
    if (s_ticket != SPLITS - 1) return;
    __threadfence();               // acquire: all batch-b atomics visible

    // ---- read importance: thread t owns columns 4t..4t+3 ----
    const float4 iv = *((const float4*)(imp + b * L) + t);

    unsigned k[4];
    {
        const float f[4] = {iv.x, iv.y, iv.z, iv.w};
#pragma unroll
        for (int i = 0; i < 4; ++i) {
            const unsigned ub = __float_as_uint(f[i]);
            k[i] = ub ^ ((ub & 0x80000000u) ? 0xFFFFFFFFu : 0x80000000u);
        }
    }

    __shared__ int      hist[256];
    __shared__ unsigned s_pref;
    __shared__ int      s_k;
    __shared__ int      wtot[8];

    if (t == 0) { s_pref = 0u; s_k = KSEL; }
    __syncthreads();

    // ---- 4-pass byte radix select: 512th-largest key + tie quota ----
#pragma unroll
    for (int pass = 0; pass < 4; ++pass) {
        const int shift = 24 - 8 * pass;
        const unsigned pref = s_pref;
        const int kcur = s_k;

        hist[t] = 0;
        __syncthreads();
#pragma unroll
        for (int i = 0; i < 4; ++i) {
            const bool active = (pass == 0) ||
                (((k[i] ^ pref) >> (shift + 8)) == 0u);
            if (active) atomicAdd(&hist[(k[i] >> shift) & 0xFF], 1);
        }
        __syncthreads();

        const int h = hist[t];
        int v = h;
#pragma unroll
        for (int d = 1; d < 32; d <<= 1) {
            const int n = __shfl_down_sync(0xffffffffu, v, d);
            if (lane + d < 32) v += n;
        }
        const int wsum = __shfl_sync(0xffffffffu, v, 0);
        if (lane == 0) wtot[wid] = wsum;
        __syncthreads();
        int above = 0;
#pragma unroll
        for (int w = 0; w < 8; ++w) if (w > wid) above += wtot[w];
        const int ge = v + above;        // active keys with bin >= t
        const int gt = ge - h;
        if (gt < kcur && ge >= kcur) {   // exactly one bin fires
            s_pref = pref | ((unsigned)t << shift);
            s_k    = kcur - gt;
        }
        __syncthreads();
    }

    const unsigned T  = s_pref;   // threshold key (512th-largest)
    const int      kq = s_k;      // tie slots (>= 1), lowest indices win

    // ---- tie ranking (ascending index) via block scan ----
    bool tie[4];
    int tiecnt = 0;
#pragma unroll
    for (int i = 0; i < 4; ++i) { tie[i] = (k[i] == T); tiecnt += tie[i]; }

    int incl = tiecnt;
#pragma unroll
    for (int d = 1; d < 32; d <<= 1) {
        const int n = __shfl_up_sync(0xffffffffu, incl, d);
        if (lane >= d) incl += n;
    }
    if (lane == 31) wtot[wid] = incl;
    __syncthreads();
    int base = 0;
#pragma unroll
    for (int w = 0; w < 8; ++w) if (w < wid) base += wtot[w];
    int trank = base + incl - tiecnt;    // exclusive prefix of ties

    bool sel[4];
    int selcnt = 0;
#pragma unroll
    for (int i = 0; i < 4; ++i) {
        bool sl = (k[i] > T);
        if (tie[i]) { sl = (trank < kq); ++trank; }
        sel[i] = sl; selcnt += sl;
    }
    __syncthreads();                     // wtot reuse

    // ---- compaction scan (ascending index) ----
    int sincl = selcnt;
#pragma unroll
    for (int d = 1; d < 32; d <<= 1) {
        const int n = __shfl_up_sync(0xffffffffu, sincl, d);
        if (lane >= d) sincl += n;
    }
    if (lane == 31) wtot[wid] = sincl;
    __syncthreads();
    int sbase = 0;
#pragma unroll
    for (int w = 0; w < 8; ++w) if (w < wid) sbase += wtot[w];
    int pos = sbase + sincl - selcnt;    // exclusive prefix

#pragma unroll
    for (int i = 0; i < 4; ++i) {
        if (sel[i]) { selidx[b * KSEL + pos] = 4 * t + i; ++pos; }
    }

    __syncthreads();   // selidx writes visible block-wide

    // ---- final attention mask for this batch (513 floats) ----
    float* mout = out + (size_t)B * (KSEL + 1) * D + (size_t)b * (KSEL + 1);
    for (int r = t; r <= KSEL; r += 256) {
        if (r == 0) mout[0] = 0.f;
        else        mout[r] = amask[(size_t)b * L + selidx[b * KSEL + r - 1]];
    }

    // ---- reset scratch for the next replay ----
    *((float4*)(imp + b * L) + t) = make_float4(0.f, 0.f, 0.f, 0.f);
    if (t == 0) count[b] = 0;
}

// ---------------------------------------------------------------------------
// Kernel 2: gather token rows (reads should now hit L2 thanks to the
// prefetch in kernel 1). grid (129, B), block 256: 4 rows/block, 64
// lanes/row, 3 independent float4 loads per thread. selidx loaded once per
// row-group and broadcast via shfl. Row 0 = class token (j=0).
// ---------------------------------------------------------------------------
__global__ void __launch_bounds__(256) gather_kernel(
    const float* __restrict__ hs, const int* __restrict__ selidx,
    float* __restrict__ out)
{
    const int rr   = threadIdx.x >> 6;       // 0..3 row slot
    const int lane = threadIdx.x & 63;       // 0..63
    const int r = blockIdx.x * 4 + rr;       // 0..515
    const int b = blockIdx.y;
    if (r > KSEL) return;

    // one selidx load per 64-lane group, broadcast
    int j = 0;
    if ((lane & 31) == 0 && r != 0) j = selidx[b * KSEL + r - 1];
    j = __shfl_sync(0xffffffffu, j, 0);

    const float4* src = (const float4*)(hs + ((size_t)b * L + j) * D) + lane;
    float4* dst = (float4*)(out + ((size_t)b * (KSEL + 1) + r) * D) + lane;

    const float4 v0 = src[0];
    const float4 v1 = src[64];
    const float4 v2 = src[128];
    dst[0]   = v0;
    dst[64]  = v1;
    dst[128] = v2;
}

// ---------------------------------------------------------------------------
extern "C" void kernel_launch(void* const* d_in, const int* in_sizes, int n_in,
                              void* d_out, int out_size)
{
    const float* hidden = (const float*)d_in[0];   // [B, L, D]
    const float* amask  = (const float*)d_in[1];   // [B, 1, 1, L]
    const float* scores = (const float*)d_in[2];   // [B, H, L, L]
    float* out = (float*)d_out;                    // tokens then mask, f32

    float* d_imp;
    int *d_selidx, *d_count;
    cudaGetSymbolAddress((void**)&d_imp,    g_imp);
    cudaGetSymbolAddress((void**)&d_selidx, g_selidx);
    cudaGetSymbolAddress((void**)&d_count,  g_count);

    dim3 gridA(B, SPLITS);
    colsum_select_kernel<<<gridA, 256>>>(
        (const float4*)scores, amask, (const char*)hidden,
        d_imp, d_selidx, d_count, out);

    dim3 gridC(129, B);
    gather_kernel<<<gridC, 256>>>(hidden, d_selidx, out);
}